// round 3
// baseline (speedup 1.0000x reference)
#include <cuda_runtime.h>
#include <cuda_bf16.h>
#include <math.h>

// Problem constants
#define BB   4
#define DIN  1024
#define CHN  512
#define HH   50
#define WW   76
#define SP   3800          // HH*WW
#define AN   9             // anchors per position
#define KTOT 34200         // SP*AN
#define NPAD 65536
#define PRE_NMS  6000
#define POST_NMS 300
#define NMS_THRESH 0.7f
#define MIN_SIZE   16.0f
#define STRIDE_F   16.0f

// ---------------- scratch (device globals; no allocation allowed) -------------
__device__ float g_wT[9 * DIN * CHN];                 // [tap][ic][oc]
__device__ float g_x [BB * CHN * SP];                 // relu(conv) output (fp32, ref-rounded)
__device__ float g_cls[BB * 18 * SP];
__device__ float g_bbox[BB * 36 * SP];
__device__ unsigned long long g_keys[BB * NPAD];
__device__ float g_boxes[BB * KTOT * 4];
__device__ float g_tb[BB * PRE_NMS * 4];              // top-k boxes
__device__ float g_ts[BB * PRE_NMS];                  // top-k scores
__device__ int   g_keep[BB * POST_NMS];

// anchor bases (py-faster-rcnn, base 16, ratios .5/1/2, scales 8/16/32)
__constant__ float c_ab[9][4] = {
    { -84.f,  -40.f,  99.f,  55.f},
    {-176.f,  -88.f, 191.f, 103.f},
    {-360.f, -184.f, 375.f, 199.f},
    { -56.f,  -56.f,  71.f,  71.f},
    {-120.f, -120.f, 135.f, 135.f},
    {-248.f, -248.f, 263.f, 263.f},
    { -36.f,  -80.f,  51.f,  95.f},
    { -80.f, -168.f,  95.f, 183.f},
    {-168.f, -344.f, 183.f, 359.f},
};

// ---------------- 0: weight transpose [oc][ic][tap] -> [tap][ic][oc] ----------
__global__ void k_transpose_w(const float* __restrict__ w) {
    int i = blockIdx.x * blockDim.x + threadIdx.x;
    const int N = 9 * DIN * CHN;
    if (i >= N) return;
    int oc  = i % CHN;
    int ic  = (i / CHN) % DIN;
    int tap = i / (CHN * DIN);
    g_wT[i] = w[(oc * DIN + ic) * 9 + tap];
}

// ---------------- 1: 3x3 conv + bias + relu, fp64 accumulation ----------------
// grid: (ceil(SP/64), CHN/64, BB), block: 256 threads, 4x4 register tile.
__global__ __launch_bounds__(256) void k_conv3x3(
    const float* __restrict__ in, const float* __restrict__ bias) {
    const int b   = blockIdx.z;
    const int oc0 = blockIdx.y * 64;
    const int sp0 = blockIdx.x * 64;
    const int t   = threadIdx.x;
    const int tx  = t & 15;     // spatial quad
    const int ty  = t >> 4;     // oc quad

    __shared__ double a_s[16][64];   // [k][oc]
    __shared__ double b_s[16][64];   // [k][sp]

    double acc[4][4];
#pragma unroll
    for (int i = 0; i < 4; i++)
#pragma unroll
        for (int j = 0; j < 4; j++) acc[i][j] = 0.0;

    const float* inb = in + (size_t)b * DIN * SP;

    // precompute this thread's b-load position
    const int ss  = t & 63;
    const int pos = sp0 + ss;
    const int ph  = pos / WW;
    const int pw  = pos - ph * WW;
    const int kb  = t >> 6;   // 0..3

    const int a_kk = t >> 4;          // 0..15
    const int a_oo = (t & 15) * 4;    // 4-wide slot

    for (int tap = 0; tap < 9; tap++) {
        const int dy = tap / 3 - 1;
        const int dx = tap % 3 - 1;
        const int hh = ph + dy;
        const int ww2 = pw + dx;
        const bool ok = (pos < SP) && (hh >= 0) && (hh < HH) && (ww2 >= 0) && (ww2 < WW);
        const int ip = hh * WW + ww2;
        const float* wtap = g_wT + (size_t)tap * DIN * CHN;

        for (int ic0 = 0; ic0 < DIN; ic0 += 16) {
            // load A tile (coalesced over oc), convert to double
            const float4 av4 = *reinterpret_cast<const float4*>(
                wtap + (size_t)(ic0 + a_kk) * CHN + oc0 + a_oo);
            a_s[a_kk][a_oo + 0] = (double)av4.x;
            a_s[a_kk][a_oo + 1] = (double)av4.y;
            a_s[a_kk][a_oo + 2] = (double)av4.z;
            a_s[a_kk][a_oo + 3] = (double)av4.w;
            // load B tile (coalesced over spatial)
#pragma unroll
            for (int u = 0; u < 4; u++) {
                const int kk = kb + u * 4;
                b_s[kk][ss] = ok ? (double)inb[(size_t)(ic0 + kk) * SP + ip] : 0.0;
            }
            __syncthreads();
#pragma unroll
            for (int kk = 0; kk < 16; kk++) {
                const double a0 = a_s[kk][ty * 4 + 0];
                const double a1 = a_s[kk][ty * 4 + 1];
                const double a2 = a_s[kk][ty * 4 + 2];
                const double a3 = a_s[kk][ty * 4 + 3];
                const double b0 = b_s[kk][tx * 4 + 0];
                const double b1 = b_s[kk][tx * 4 + 1];
                const double b2 = b_s[kk][tx * 4 + 2];
                const double b3 = b_s[kk][tx * 4 + 3];
                acc[0][0] = fma(a0, b0, acc[0][0]); acc[0][1] = fma(a0, b1, acc[0][1]);
                acc[0][2] = fma(a0, b2, acc[0][2]); acc[0][3] = fma(a0, b3, acc[0][3]);
                acc[1][0] = fma(a1, b0, acc[1][0]); acc[1][1] = fma(a1, b1, acc[1][1]);
                acc[1][2] = fma(a1, b2, acc[1][2]); acc[1][3] = fma(a1, b3, acc[1][3]);
                acc[2][0] = fma(a2, b0, acc[2][0]); acc[2][1] = fma(a2, b1, acc[2][1]);
                acc[2][2] = fma(a2, b2, acc[2][2]); acc[2][3] = fma(a2, b3, acc[2][3]);
                acc[3][0] = fma(a3, b0, acc[3][0]); acc[3][1] = fma(a3, b1, acc[3][1]);
                acc[3][2] = fma(a3, b2, acc[3][2]); acc[3][3] = fma(a3, b3, acc[3][3]);
            }
            __syncthreads();
        }
    }

    // epilogue: round conv result to fp32 (ref tensor boundary), fp32 bias + relu
#pragma unroll
    for (int i = 0; i < 4; i++) {
        const int oc = oc0 + ty * 4 + i;
        const float bv = bias[oc];
        float* outp = g_x + ((size_t)b * CHN + oc) * SP;
#pragma unroll
        for (int j = 0; j < 4; j++) {
            const int p = sp0 + tx * 4 + j;
            if (p < SP) {
                const float cf = (float)acc[i][j];
                const float v  = __fadd_rn(cf, bv);
                outp[p] = v > 0.f ? v : 0.f;
            }
        }
    }
}

// ---------------- 2: 1x1 cls + bbox heads, fp64 accumulation ------------------
// grid: (ceil(SP/256), 54, BB)
__global__ __launch_bounds__(256) void k_heads(
    const float* __restrict__ cls_w, const float* __restrict__ cls_b,
    const float* __restrict__ bbox_w, const float* __restrict__ bbox_b) {
    const int pos = blockIdx.x * blockDim.x + threadIdx.x;
    const int o   = blockIdx.y;
    const int b   = blockIdx.z;
    if (pos >= SP) return;

    const float* wp;
    float bv;
    if (o < 18) { wp = cls_w + (size_t)o * CHN;        bv = cls_b[o]; }
    else        { wp = bbox_w + (size_t)(o - 18) * CHN; bv = bbox_b[o - 18]; }

    const float* xp = g_x + (size_t)b * CHN * SP + pos;
    double acc = 0.0;
#pragma unroll 8
    for (int c = 0; c < CHN; c++) {
        acc = fma((double)__ldg(xp + (size_t)c * SP), (double)__ldg(wp + c), acc);
    }
    const float r = __fadd_rn((float)acc, bv);
    if (o < 18) g_cls[((size_t)b * 18 + o) * SP + pos] = r;
    else        g_bbox[((size_t)b * 36 + (o - 18)) * SP + pos] = r;
}

// ---------------- 3: decode + clip + filter + key build ----------------------
__device__ __forceinline__ unsigned int fmono(float f) {
    unsigned int u = __float_as_uint(f);
    return (u & 0x80000000u) ? ~u : (u | 0x80000000u);
}
__device__ __forceinline__ float fmono_inv(unsigned int u) {
    unsigned int v = (u & 0x80000000u) ? (u & 0x7FFFFFFFu) : ~u;
    return __uint_as_float(v);
}

__global__ void k_decode(const float* __restrict__ im_info) {
    const int i = blockIdx.x * blockDim.x + threadIdx.x;
    const int b = blockIdx.y;
    if (i >= NPAD) return;
    if (i >= KTOT) { g_keys[(size_t)b * NPAD + i] = 0ull; return; }

    const int pos = i / AN;
    const int a   = i - pos * AN;
    const int h   = pos / WW;
    const int w   = pos - h * WW;

    // fg prob: exact jax softmax op order (max-subtract, expf=libdevice, fp32 div)
    const float c0 = g_cls[((size_t)b * 18 + a) * SP + pos];
    const float c1 = g_cls[((size_t)b * 18 + 9 + a) * SP + pos];
    const float m  = fmaxf(c0, c1);
    const float e0 = expf(__fsub_rn(c0, m));
    const float e1 = expf(__fsub_rn(c1, m));
    const float fg = e1 / __fadd_rn(e0, e1);

    const float d0 = g_bbox[((size_t)b * 36 + a * 4 + 0) * SP + pos];
    const float d1 = g_bbox[((size_t)b * 36 + a * 4 + 1) * SP + pos];
    const float d2 = g_bbox[((size_t)b * 36 + a * 4 + 2) * SP + pos];
    const float d3 = g_bbox[((size_t)b * 36 + a * 4 + 3) * SP + pos];

    const float sx = w * STRIDE_F, sy = h * STRIDE_F;
    const float ax1 = __fadd_rn(c_ab[a][0], sx), ay1 = __fadd_rn(c_ab[a][1], sy);
    const float ax2 = __fadd_rn(c_ab[a][2], sx), ay2 = __fadd_rn(c_ab[a][3], sy);
    const float aw  = __fadd_rn(__fsub_rn(ax2, ax1), 1.f);
    const float ah  = __fadd_rn(__fsub_rn(ay2, ay1), 1.f);
    const float axc = __fadd_rn(ax1, __fmul_rn(0.5f, aw));
    const float ayc = __fadd_rn(ay1, __fmul_rn(0.5f, ah));

    // no FMA contraction: mirror jax's separate mul/add roundings
    const float cx  = __fadd_rn(axc, __fmul_rn(d0, aw));
    const float cy  = __fadd_rn(ayc, __fmul_rn(d1, ah));
    const float pw  = __fmul_rn(expf(d2), aw);
    const float phh = __fmul_rn(expf(d3), ah);

    float x1 = __fsub_rn(cx, __fmul_rn(0.5f, pw));
    float y1 = __fsub_rn(cy, __fmul_rn(0.5f, phh));
    float x2 = __fadd_rn(cx, __fmul_rn(0.5f, pw));
    float y2 = __fadd_rn(cy, __fmul_rn(0.5f, phh));

    const float i0 = im_info[b * 3 + 0];
    const float i1 = im_info[b * 3 + 1];
    const float i2 = im_info[b * 3 + 2];
    x1 = fminf(fmaxf(x1, 0.f), __fsub_rn(i1, 1.f));
    x2 = fminf(fmaxf(x2, 0.f), __fsub_rn(i1, 1.f));
    y1 = fminf(fmaxf(y1, 0.f), __fsub_rn(i0, 1.f));
    y2 = fminf(fmaxf(y2, 0.f), __fsub_rn(i0, 1.f));

    const float ws = __fadd_rn(__fsub_rn(x2, x1), 1.f);
    const float hs = __fadd_rn(__fsub_rn(y2, y1), 1.f);
    const float ms = __fmul_rn(MIN_SIZE, i2);
    const float score = (ws >= ms && hs >= ms) ? fg : -INFINITY;

    float* bo = g_boxes + ((size_t)b * KTOT + i) * 4;
    bo[0] = x1; bo[1] = y1; bo[2] = x2; bo[3] = y2;

    g_keys[(size_t)b * NPAD + i] =
        ((unsigned long long)fmono(score) << 32) | (unsigned long long)(0xFFFFFFFFu - (unsigned)i);
}

// ---------------- 4: bitonic sort (descending), 1 block per image ------------
__global__ __launch_bounds__(1024) void k_sort() {
    unsigned long long* k = g_keys + (size_t)blockIdx.x * NPAD;
    const int N = NPAD;
    for (int len = 2; len <= N; len <<= 1) {
        for (int j = len >> 1; j > 0; j >>= 1) {
            for (int i = threadIdx.x; i < N; i += blockDim.x) {
                const int ixj = i ^ j;
                if (ixj > i) {
                    const unsigned long long a = k[i], c = k[ixj];
                    const bool desc = ((i & len) == 0);
                    const bool sw = desc ? (a < c) : (a > c);
                    if (sw) { k[i] = c; k[ixj] = a; }
                }
            }
            __syncthreads();
        }
    }
}

// ---------------- 5: gather top-k --------------------------------------------
__global__ void k_gather() {
    const int i = blockIdx.x * blockDim.x + threadIdx.x;
    const int b = blockIdx.y;
    if (i >= PRE_NMS) return;
    const unsigned long long key = g_keys[(size_t)b * NPAD + i];
    const unsigned int idx = 0xFFFFFFFFu - (unsigned int)(key & 0xFFFFFFFFull);
    g_ts[(size_t)b * PRE_NMS + i] = fmono_inv((unsigned int)(key >> 32));
    const float* src = g_boxes + ((size_t)b * KTOT + idx) * 4;
    float* dst = g_tb + ((size_t)b * PRE_NMS + i) * 4;
    dst[0] = src[0]; dst[1] = src[1]; dst[2] = src[2]; dst[3] = src[3];
}

// ---------------- 6: greedy NMS, 1 block per image ---------------------------
__global__ __launch_bounds__(1024) void k_nms() {
    const int b = blockIdx.x;
    const int tid = threadIdx.x;
    __shared__ unsigned char alive[PRE_NMS];
    __shared__ int s_head, s_cur;

    const float* ts = g_ts + (size_t)b * PRE_NMS;
    const float* tb = g_tb + (size_t)b * PRE_NMS * 4;

    for (int i = tid; i < PRE_NMS; i += blockDim.x)
        alive[i] = (ts[i] != -INFINITY) ? 1 : 0;
    if (tid == 0) s_head = 0;
    __syncthreads();

    for (int r = 0; r < POST_NMS; r++) {
        if (tid == 0) {
            int h = s_head;
            while (h < PRE_NMS && !alive[h]) h++;
            s_head = h;
            s_cur = (h < PRE_NMS) ? h : 0;
            g_keep[b * POST_NMS + r] = s_cur;
        }
        __syncthreads();
        const int j = s_cur;
        const float jx1 = tb[j * 4 + 0], jy1 = tb[j * 4 + 1];
        const float jx2 = tb[j * 4 + 2], jy2 = tb[j * 4 + 3];
        const float ja = __fmul_rn(__fadd_rn(__fsub_rn(jx2, jx1), 1.f),
                                   __fadd_rn(__fsub_rn(jy2, jy1), 1.f));
        for (int i = tid; i < PRE_NMS; i += blockDim.x) {
            if (!alive[i]) continue;
            const float x1 = tb[i * 4 + 0], y1 = tb[i * 4 + 1];
            const float x2 = tb[i * 4 + 2], y2 = tb[i * 4 + 3];
            const float xx1 = fmaxf(jx1, x1), yy1 = fmaxf(jy1, y1);
            const float xx2 = fminf(jx2, x2), yy2 = fminf(jy2, y2);
            const float iw = fmaxf(0.f, __fadd_rn(__fsub_rn(xx2, xx1), 1.f));
            const float ih = fmaxf(0.f, __fadd_rn(__fsub_rn(yy2, yy1), 1.f));
            const float inter = __fmul_rn(iw, ih);
            const float ia = __fmul_rn(__fadd_rn(__fsub_rn(x2, x1), 1.f),
                                       __fadd_rn(__fsub_rn(y2, y1), 1.f));
            const float iou = inter / __fsub_rn(__fadd_rn(ja, ia), inter);
            if (iou > NMS_THRESH) alive[i] = 0;
        }
        __syncthreads();
    }
}

// ---------------- 7: write outputs -------------------------------------------
// out layout: [B*300] scores then [B*300*4] boxes
__global__ void k_writeout(float* __restrict__ out) {
    const int t = blockIdx.x * blockDim.x + threadIdx.x;
    if (t >= BB * POST_NMS) return;
    const int b = t / POST_NMS;
    const int j = g_keep[t];
    out[t] = g_ts[(size_t)b * PRE_NMS + j];
    const float* src = g_tb + ((size_t)b * PRE_NMS + j) * 4;
    float* dst = out + BB * POST_NMS + (size_t)t * 4;
    dst[0] = src[0]; dst[1] = src[1]; dst[2] = src[2]; dst[3] = src[3];
}

// ---------------- launch ------------------------------------------------------
extern "C" void kernel_launch(void* const* d_in, const int* in_sizes, int n_in,
                              void* d_out, int out_size) {
    const float* base_feat = (const float*)d_in[0];
    const float* im_info   = (const float*)d_in[1];
    // d_in[2] gt_boxes, d_in[3] num_boxes: unused
    const float* conv_w    = (const float*)d_in[4];
    const float* conv_b    = (const float*)d_in[5];
    const float* cls_w     = (const float*)d_in[6];
    const float* cls_b     = (const float*)d_in[7];
    const float* bbox_w    = (const float*)d_in[8];
    const float* bbox_b    = (const float*)d_in[9];
    float* out = (float*)d_out;

    {   // weight transpose
        const int n = 9 * DIN * CHN;
        k_transpose_w<<<(n + 255) / 256, 256>>>(conv_w);
    }
    {   // conv (fp64 accumulate)
        dim3 grid((SP + 63) / 64, CHN / 64, BB);
        k_conv3x3<<<grid, 256>>>(base_feat, conv_b);
    }
    {   // heads (fp64 accumulate)
        dim3 grid((SP + 255) / 256, 54, BB);
        k_heads<<<grid, 256>>>(cls_w, cls_b, bbox_w, bbox_b);
    }
    {   // decode
        dim3 grid((NPAD + 255) / 256, BB);
        k_decode<<<grid, 256>>>(im_info);
    }
    k_sort<<<BB, 1024>>>();
    {
        dim3 grid((PRE_NMS + 255) / 256, BB);
        k_gather<<<grid, 256>>>();
    }
    k_nms<<<BB, 1024>>>();
    k_writeout<<<(BB * POST_NMS + 255) / 256, 256>>>(out);
}

// round 4
// speedup vs baseline: 14.4184x; 14.4184x over previous
#include <cuda_runtime.h>
#include <cuda_bf16.h>
#include <math.h>

// Problem constants
#define BB   4
#define DIN  1024
#define CHN  512
#define HH   50
#define WW   76
#define SP   3800          // HH*WW
#define AN   9             // anchors per position
#define KTOT 34200         // SP*AN
#define NPAD 65536
#define PRE_NMS  6000
#define POST_NMS 300
#define NMS_THRESH 0.7f
#define MIN_SIZE   16.0f
#define STRIDE_F   16.0f

// ---------------- scratch (device globals; no allocation allowed) -------------
__device__ float g_wT[9 * DIN * CHN];                 // [tap][ic][oc]
__device__ float g_x [BB * CHN * SP];                 // relu(conv) output
__device__ float g_cls[BB * 18 * SP];
__device__ float g_bbox[BB * 36 * SP];
__device__ unsigned long long g_keys[BB * NPAD];
__device__ float g_boxes[BB * KTOT * 4];
__device__ float g_tb[BB * PRE_NMS * 4];              // top-k boxes
__device__ float g_ts[BB * PRE_NMS];                  // top-k scores
__device__ int   g_keep[BB * POST_NMS];

// anchor bases (py-faster-rcnn, base 16, ratios .5/1/2, scales 8/16/32)
__constant__ float c_ab[9][4] = {
    { -84.f,  -40.f,  99.f,  55.f},
    {-176.f,  -88.f, 191.f, 103.f},
    {-360.f, -184.f, 375.f, 199.f},
    { -56.f,  -56.f,  71.f,  71.f},
    {-120.f, -120.f, 135.f, 135.f},
    {-248.f, -248.f, 263.f, 263.f},
    { -36.f,  -80.f,  51.f,  95.f},
    { -80.f, -168.f,  95.f, 183.f},
    {-168.f, -344.f, 183.f, 359.f},
};

// exact twoSum fold of chunk value v into (hi, lo) double-float accumulator
#define TWOSUM_FOLD(hi, lo, v)                                          \
    {                                                                    \
        const float _s = __fadd_rn((hi), (v));                           \
        const float _z = __fsub_rn(_s, (hi));                            \
        const float _e = __fadd_rn(__fsub_rn((hi), __fsub_rn(_s, _z)),   \
                                   __fsub_rn((v), _z));                  \
        (hi) = _s;                                                       \
        (lo) = __fadd_rn((lo), _e);                                      \
    }

// ---------------- 0: weight transpose [oc][ic][tap] -> [tap][ic][oc] ----------
__global__ void k_transpose_w(const float* __restrict__ w) {
    int i = blockIdx.x * blockDim.x + threadIdx.x;
    const int N = 9 * DIN * CHN;
    if (i >= N) return;
    int oc  = i % CHN;
    int ic  = (i / CHN) % DIN;
    int tap = i / (CHN * DIN);
    g_wT[i] = w[(oc * DIN + ic) * 9 + tap];
}

// ---------------- 1: 3x3 conv + bias + relu ----------------------------------
// fp32 FFMA in chunks of 8 over K, exact twoSum fold into double-float acc.
// grid: (ceil(SP/64), CHN/64, BB), block: 256 threads, 4x4 register tile.
__global__ __launch_bounds__(256) void k_conv3x3(
    const float* __restrict__ in, const float* __restrict__ bias) {
    const int b   = blockIdx.z;
    const int oc0 = blockIdx.y * 64;
    const int sp0 = blockIdx.x * 64;
    const int t   = threadIdx.x;
    const int tx  = t & 15;     // spatial quad
    const int ty  = t >> 4;     // oc quad

    __shared__ float a_s[16][64];   // [k][oc]
    __shared__ float b_s[16][64];   // [k][sp]

    float hi[4][4], lo[4][4];
#pragma unroll
    for (int i = 0; i < 4; i++)
#pragma unroll
        for (int j = 0; j < 4; j++) { hi[i][j] = 0.f; lo[i][j] = 0.f; }

    const float* inb = in + (size_t)b * DIN * SP;

    const int ss  = t & 63;
    const int pos = sp0 + ss;
    const int ph  = pos / WW;
    const int pw  = pos - ph * WW;
    const int kb  = t >> 6;   // 0..3

    const int a_kk = t >> 4;          // 0..15
    const int a_oo = (t & 15) * 4;    // float4 slot

    for (int tap = 0; tap < 9; tap++) {
        const int dy = tap / 3 - 1;
        const int dx = tap % 3 - 1;
        const int hh = ph + dy;
        const int ww2 = pw + dx;
        const bool ok = (pos < SP) && (hh >= 0) && (hh < HH) && (ww2 >= 0) && (ww2 < WW);
        const int ip = hh * WW + ww2;
        const float* wtap = g_wT + (size_t)tap * DIN * CHN;

        for (int ic0 = 0; ic0 < DIN; ic0 += 16) {
            // load A tile (coalesced over oc)
            const float4 av4 = *reinterpret_cast<const float4*>(
                wtap + (size_t)(ic0 + a_kk) * CHN + oc0 + a_oo);
            *reinterpret_cast<float4*>(&a_s[a_kk][a_oo]) = av4;
            // load B tile (coalesced over spatial)
#pragma unroll
            for (int u = 0; u < 4; u++) {
                const int kk = kb + u * 4;
                b_s[kk][ss] = ok ? inb[(size_t)(ic0 + kk) * SP + ip] : 0.f;
            }
            __syncthreads();

#pragma unroll
            for (int half = 0; half < 2; half++) {
                float c[4][4];
#pragma unroll
                for (int i = 0; i < 4; i++)
#pragma unroll
                    for (int j = 0; j < 4; j++) c[i][j] = 0.f;
#pragma unroll
                for (int kk2 = 0; kk2 < 8; kk2++) {
                    const int kk = half * 8 + kk2;
                    const float4 av = *reinterpret_cast<const float4*>(&a_s[kk][ty * 4]);
                    const float4 bv = *reinterpret_cast<const float4*>(&b_s[kk][tx * 4]);
                    c[0][0] = fmaf(av.x, bv.x, c[0][0]); c[0][1] = fmaf(av.x, bv.y, c[0][1]);
                    c[0][2] = fmaf(av.x, bv.z, c[0][2]); c[0][3] = fmaf(av.x, bv.w, c[0][3]);
                    c[1][0] = fmaf(av.y, bv.x, c[1][0]); c[1][1] = fmaf(av.y, bv.y, c[1][1]);
                    c[1][2] = fmaf(av.y, bv.z, c[1][2]); c[1][3] = fmaf(av.y, bv.w, c[1][3]);
                    c[2][0] = fmaf(av.z, bv.x, c[2][0]); c[2][1] = fmaf(av.z, bv.y, c[2][1]);
                    c[2][2] = fmaf(av.z, bv.z, c[2][2]); c[2][3] = fmaf(av.z, bv.w, c[2][3]);
                    c[3][0] = fmaf(av.w, bv.x, c[3][0]); c[3][1] = fmaf(av.w, bv.y, c[3][1]);
                    c[3][2] = fmaf(av.w, bv.z, c[3][2]); c[3][3] = fmaf(av.w, bv.w, c[3][3]);
                }
#pragma unroll
                for (int i = 0; i < 4; i++)
#pragma unroll
                    for (int j = 0; j < 4; j++) {
                        TWOSUM_FOLD(hi[i][j], lo[i][j], c[i][j]);
                    }
            }
            __syncthreads();
        }
    }

    // epilogue: collapse double-float, fp32 bias + relu (ref op order)
#pragma unroll
    for (int i = 0; i < 4; i++) {
        const int oc = oc0 + ty * 4 + i;
        const float bv = bias[oc];
        float* outp = g_x + ((size_t)b * CHN + oc) * SP;
#pragma unroll
        for (int j = 0; j < 4; j++) {
            const int p = sp0 + tx * 4 + j;
            if (p < SP) {
                const float cf = __fadd_rn(hi[i][j], lo[i][j]);
                const float v  = __fadd_rn(cf, bv);
                outp[p] = v > 0.f ? v : 0.f;
            }
        }
    }
}

// ---------------- 2: 1x1 cls + bbox heads (chunked fp32 + twoSum) -------------
// grid: (ceil(SP/256), 54, BB)
__global__ __launch_bounds__(256) void k_heads(
    const float* __restrict__ cls_w, const float* __restrict__ cls_b,
    const float* __restrict__ bbox_w, const float* __restrict__ bbox_b) {
    const int pos = blockIdx.x * blockDim.x + threadIdx.x;
    const int o   = blockIdx.y;
    const int b   = blockIdx.z;
    if (pos >= SP) return;

    const float* wp;
    float bv;
    if (o < 18) { wp = cls_w + (size_t)o * CHN;        bv = cls_b[o]; }
    else        { wp = bbox_w + (size_t)(o - 18) * CHN; bv = bbox_b[o - 18]; }

    const float* xp = g_x + (size_t)b * CHN * SP + pos;
    float hi = 0.f, lo = 0.f;
    for (int c0 = 0; c0 < CHN; c0 += 8) {
        float c = 0.f;
#pragma unroll
        for (int k = 0; k < 8; k++) {
            c = fmaf(__ldg(xp + (size_t)(c0 + k) * SP), __ldg(wp + c0 + k), c);
        }
        TWOSUM_FOLD(hi, lo, c);
    }
    const float r = __fadd_rn(__fadd_rn(hi, lo), bv);
    if (o < 18) g_cls[((size_t)b * 18 + o) * SP + pos] = r;
    else        g_bbox[((size_t)b * 36 + (o - 18)) * SP + pos] = r;
}

// ---------------- 3: decode + clip + filter + key build ----------------------
__device__ __forceinline__ unsigned int fmono(float f) {
    unsigned int u = __float_as_uint(f);
    return (u & 0x80000000u) ? ~u : (u | 0x80000000u);
}
__device__ __forceinline__ float fmono_inv(unsigned int u) {
    unsigned int v = (u & 0x80000000u) ? (u & 0x7FFFFFFFu) : ~u;
    return __uint_as_float(v);
}

__global__ void k_decode(const float* __restrict__ im_info) {
    const int i = blockIdx.x * blockDim.x + threadIdx.x;
    const int b = blockIdx.y;
    if (i >= NPAD) return;
    if (i >= KTOT) { g_keys[(size_t)b * NPAD + i] = 0ull; return; }

    const int pos = i / AN;
    const int a   = i - pos * AN;
    const int h   = pos / WW;
    const int w   = pos - h * WW;

    // fg prob: exact jax softmax op order
    const float c0 = g_cls[((size_t)b * 18 + a) * SP + pos];
    const float c1 = g_cls[((size_t)b * 18 + 9 + a) * SP + pos];
    const float m  = fmaxf(c0, c1);
    const float e0 = expf(__fsub_rn(c0, m));
    const float e1 = expf(__fsub_rn(c1, m));
    const float fg = e1 / __fadd_rn(e0, e1);

    const float d0 = g_bbox[((size_t)b * 36 + a * 4 + 0) * SP + pos];
    const float d1 = g_bbox[((size_t)b * 36 + a * 4 + 1) * SP + pos];
    const float d2 = g_bbox[((size_t)b * 36 + a * 4 + 2) * SP + pos];
    const float d3 = g_bbox[((size_t)b * 36 + a * 4 + 3) * SP + pos];

    const float sx = w * STRIDE_F, sy = h * STRIDE_F;
    const float ax1 = __fadd_rn(c_ab[a][0], sx), ay1 = __fadd_rn(c_ab[a][1], sy);
    const float ax2 = __fadd_rn(c_ab[a][2], sx), ay2 = __fadd_rn(c_ab[a][3], sy);
    const float aw  = __fadd_rn(__fsub_rn(ax2, ax1), 1.f);
    const float ah  = __fadd_rn(__fsub_rn(ay2, ay1), 1.f);
    const float axc = __fadd_rn(ax1, __fmul_rn(0.5f, aw));
    const float ayc = __fadd_rn(ay1, __fmul_rn(0.5f, ah));

    const float cx  = __fadd_rn(axc, __fmul_rn(d0, aw));
    const float cy  = __fadd_rn(ayc, __fmul_rn(d1, ah));
    const float pw  = __fmul_rn(expf(d2), aw);
    const float phh = __fmul_rn(expf(d3), ah);

    float x1 = __fsub_rn(cx, __fmul_rn(0.5f, pw));
    float y1 = __fsub_rn(cy, __fmul_rn(0.5f, phh));
    float x2 = __fadd_rn(cx, __fmul_rn(0.5f, pw));
    float y2 = __fadd_rn(cy, __fmul_rn(0.5f, phh));

    const float i0 = im_info[b * 3 + 0];
    const float i1 = im_info[b * 3 + 1];
    const float i2 = im_info[b * 3 + 2];
    x1 = fminf(fmaxf(x1, 0.f), __fsub_rn(i1, 1.f));
    x2 = fminf(fmaxf(x2, 0.f), __fsub_rn(i1, 1.f));
    y1 = fminf(fmaxf(y1, 0.f), __fsub_rn(i0, 1.f));
    y2 = fminf(fmaxf(y2, 0.f), __fsub_rn(i0, 1.f));

    const float ws = __fadd_rn(__fsub_rn(x2, x1), 1.f);
    const float hs = __fadd_rn(__fsub_rn(y2, y1), 1.f);
    const float ms = __fmul_rn(MIN_SIZE, i2);
    const float score = (ws >= ms && hs >= ms) ? fg : -INFINITY;

    float* bo = g_boxes + ((size_t)b * KTOT + i) * 4;
    bo[0] = x1; bo[1] = y1; bo[2] = x2; bo[3] = y2;

    g_keys[(size_t)b * NPAD + i] =
        ((unsigned long long)fmono(score) << 32) | (unsigned long long)(0xFFFFFFFFu - (unsigned)i);
}

// ---------------- 4: bitonic sort (descending), 1 block per image ------------
__global__ __launch_bounds__(1024) void k_sort() {
    unsigned long long* k = g_keys + (size_t)blockIdx.x * NPAD;
    const int N = NPAD;
    for (int len = 2; len <= N; len <<= 1) {
        for (int j = len >> 1; j > 0; j >>= 1) {
            for (int i = threadIdx.x; i < N; i += blockDim.x) {
                const int ixj = i ^ j;
                if (ixj > i) {
                    const unsigned long long a = k[i], c = k[ixj];
                    const bool desc = ((i & len) == 0);
                    const bool sw = desc ? (a < c) : (a > c);
                    if (sw) { k[i] = c; k[ixj] = a; }
                }
            }
            __syncthreads();
        }
    }
}

// ---------------- 5: gather top-k --------------------------------------------
__global__ void k_gather() {
    const int i = blockIdx.x * blockDim.x + threadIdx.x;
    const int b = blockIdx.y;
    if (i >= PRE_NMS) return;
    const unsigned long long key = g_keys[(size_t)b * NPAD + i];
    const unsigned int idx = 0xFFFFFFFFu - (unsigned int)(key & 0xFFFFFFFFull);
    g_ts[(size_t)b * PRE_NMS + i] = fmono_inv((unsigned int)(key >> 32));
    const float* src = g_boxes + ((size_t)b * KTOT + idx) * 4;
    float* dst = g_tb + ((size_t)b * PRE_NMS + i) * 4;
    dst[0] = src[0]; dst[1] = src[1]; dst[2] = src[2]; dst[3] = src[3];
}

// ---------------- 6: greedy NMS, 1 block per image ---------------------------
__global__ __launch_bounds__(1024) void k_nms() {
    const int b = blockIdx.x;
    const int tid = threadIdx.x;
    __shared__ unsigned char alive[PRE_NMS];
    __shared__ int s_head, s_cur;

    const float* ts = g_ts + (size_t)b * PRE_NMS;
    const float* tb = g_tb + (size_t)b * PRE_NMS * 4;

    for (int i = tid; i < PRE_NMS; i += blockDim.x)
        alive[i] = (ts[i] != -INFINITY) ? 1 : 0;
    if (tid == 0) s_head = 0;
    __syncthreads();

    for (int r = 0; r < POST_NMS; r++) {
        if (tid == 0) {
            int h = s_head;
            while (h < PRE_NMS && !alive[h]) h++;
            s_head = h;
            s_cur = (h < PRE_NMS) ? h : 0;
            g_keep[b * POST_NMS + r] = s_cur;
        }
        __syncthreads();
        const int j = s_cur;
        const float jx1 = tb[j * 4 + 0], jy1 = tb[j * 4 + 1];
        const float jx2 = tb[j * 4 + 2], jy2 = tb[j * 4 + 3];
        const float ja = __fmul_rn(__fadd_rn(__fsub_rn(jx2, jx1), 1.f),
                                   __fadd_rn(__fsub_rn(jy2, jy1), 1.f));
        for (int i = tid; i < PRE_NMS; i += blockDim.x) {
            if (!alive[i]) continue;
            const float x1 = tb[i * 4 + 0], y1 = tb[i * 4 + 1];
            const float x2 = tb[i * 4 + 2], y2 = tb[i * 4 + 3];
            const float xx1 = fmaxf(jx1, x1), yy1 = fmaxf(jy1, y1);
            const float xx2 = fminf(jx2, x2), yy2 = fminf(jy2, y2);
            const float iw = fmaxf(0.f, __fadd_rn(__fsub_rn(xx2, xx1), 1.f));
            const float ih = fmaxf(0.f, __fadd_rn(__fsub_rn(yy2, yy1), 1.f));
            const float inter = __fmul_rn(iw, ih);
            const float ia = __fmul_rn(__fadd_rn(__fsub_rn(x2, x1), 1.f),
                                       __fadd_rn(__fsub_rn(y2, y1), 1.f));
            const float iou = inter / __fsub_rn(__fadd_rn(ja, ia), inter);
            if (iou > NMS_THRESH) alive[i] = 0;
        }
        __syncthreads();
    }
}

// ---------------- 7: write outputs -------------------------------------------
// out layout: [B*300] scores then [B*300*4] boxes
__global__ void k_writeout(float* __restrict__ out) {
    const int t = blockIdx.x * blockDim.x + threadIdx.x;
    if (t >= BB * POST_NMS) return;
    const int b = t / POST_NMS;
    const int j = g_keep[t];
    out[t] = g_ts[(size_t)b * PRE_NMS + j];
    const float* src = g_tb + ((size_t)b * PRE_NMS + j) * 4;
    float* dst = out + BB * POST_NMS + (size_t)t * 4;
    dst[0] = src[0]; dst[1] = src[1]; dst[2] = src[2]; dst[3] = src[3];
}

// ---------------- launch ------------------------------------------------------
extern "C" void kernel_launch(void* const* d_in, const int* in_sizes, int n_in,
                              void* d_out, int out_size) {
    const float* base_feat = (const float*)d_in[0];
    const float* im_info   = (const float*)d_in[1];
    // d_in[2] gt_boxes, d_in[3] num_boxes: unused
    const float* conv_w    = (const float*)d_in[4];
    const float* conv_b    = (const float*)d_in[5];
    const float* cls_w     = (const float*)d_in[6];
    const float* cls_b     = (const float*)d_in[7];
    const float* bbox_w    = (const float*)d_in[8];
    const float* bbox_b    = (const float*)d_in[9];
    float* out = (float*)d_out;

    {   // weight transpose
        const int n = 9 * DIN * CHN;
        k_transpose_w<<<(n + 255) / 256, 256>>>(conv_w);
    }
    {   // conv (fp32 chunked + twoSum)
        dim3 grid((SP + 63) / 64, CHN / 64, BB);
        k_conv3x3<<<grid, 256>>>(base_feat, conv_b);
    }
    {   // heads (fp32 chunked + twoSum)
        dim3 grid((SP + 255) / 256, 54, BB);
        k_heads<<<grid, 256>>>(cls_w, cls_b, bbox_w, bbox_b);
    }
    {   // decode
        dim3 grid((NPAD + 255) / 256, BB);
        k_decode<<<grid, 256>>>(im_info);
    }
    k_sort<<<BB, 1024>>>();
    {
        dim3 grid((PRE_NMS + 255) / 256, BB);
        k_gather<<<grid, 256>>>();
    }
    k_nms<<<BB, 1024>>>();
    k_writeout<<<(BB * POST_NMS + 255) / 256, 256>>>(out);
}